// round 15
// baseline (speedup 1.0000x reference)
#include <cuda_runtime.h>
#include <cuda_fp16.h>
#include <cstdint>

#define H 4
#define KCODES 8192
#define DFULL 1024
#define DHEAD 256
#define BATCH 8192

#define TILE_M 128
#define TILE_N 128
#define NBLK (KCODES / TILE_N)   // 64
#define KCB 128                  // chunk width in BYTES (s8 elements)
#define NCHUNK (DHEAD / KCB)     // 2
#define LDB 144                  // smem row stride in bytes (128 + 16 pad)
#define MARGIN 6.0f
#define MAXCAND 256

#define SCALE_X 25.0f
#define SCALE_E 50.0f
#define INV_SC (1.0f / (SCALE_X * SCALE_E))

#define ST_BYTES (TILE_M * LDB)              // 18432 B per stage per tensor
#define SMEM_DYN (4 * ST_BYTES)              // 73728 B: A0,A1,B0,B1

// Scratch
__device__ float g_e2[H * KCODES];
__device__ signed char g_xq[(size_t)BATCH * DFULL];
__device__ signed char g_cq[(size_t)H * KCODES * DHEAD];
__device__ __half g_distH[(size_t)BATCH * H * KCODES];
__device__ float g_blkminF[(size_t)BATCH * H * NBLK];

__device__ __forceinline__ uint32_t float_key(float f) {
    unsigned ub = __float_as_uint(f);
    return (ub & 0x80000000u) ? ~ub : (ub | 0x80000000u);
}
__device__ __forceinline__ int q8(float v, float s) {
    int q = __float2int_rn(v * s);
    return max(-127, min(127, q));
}
__device__ __forceinline__ uint32_t pack4(int a, int b, int c, int d) {
    return (uint32_t)(a & 0xFF) | ((uint32_t)(b & 0xFF) << 8) |
           ((uint32_t)(c & 0xFF) << 16) | ((uint32_t)(d & 0xFF) << 24);
}

#define MMA_S8(c, a, b0, b1) \
    asm volatile("mma.sync.aligned.m16n8k32.row.col.s32.s8.s8.s32 " \
        "{%0,%1,%2,%3}, {%4,%5,%6,%7}, {%8,%9}, {%0,%1,%2,%3};" \
        : "+r"((c)[0]), "+r"((c)[1]), "+r"((c)[2]), "+r"((c)[3]) \
        : "r"((a)[0]), "r"((a)[1]), "r"((a)[2]), "r"((a)[3]), \
          "r"(b0), "r"(b1))

#define LDSM_X4(r0, r1, r2, r3, addr) \
    asm volatile("ldmatrix.sync.aligned.m8n8.x4.shared.b16 {%0,%1,%2,%3}, [%4];" \
        : "=r"(r0), "=r"(r1), "=r"(r2), "=r"(r3) : "r"(addr))

#define CP_ASYNC16(dst, src) \
    asm volatile("cp.async.cg.shared.global [%0], [%1], 16;" :: "r"(dst), "l"(src))
#define CP_COMMIT() asm volatile("cp.async.commit_group;" ::: "memory")
#define CP_WAIT(n)  asm volatile("cp.async.wait_group %0;" :: "n"(n) : "memory")

// ---------------------------------------------------------------------------
// Merged prep: blocks [0,4096) -> e2 + codebook s8 quant (warp per code row);
// blocks [4096,8192) -> x s8 quant (8 floats per thread).
// ---------------------------------------------------------------------------
#define E2_BLOCKS 4096
__global__ void prep_kernel(const float* __restrict__ x, const float* __restrict__ cb) {
    if (blockIdx.x < E2_BLOCKS) {
        int warp = (blockIdx.x * blockDim.x + threadIdx.x) >> 5;
        int lane = threadIdx.x & 31;
        const float4* p = (const float4*)(cb + (size_t)warp * DHEAD);
        float4 v0 = p[lane * 2];
        float4 v1 = p[lane * 2 + 1];
        float s = v0.x * v0.x + v0.y * v0.y + v0.z * v0.z + v0.w * v0.w
                + v1.x * v1.x + v1.y * v1.y + v1.z * v1.z + v1.w * v1.w;
#pragma unroll
        for (int o = 16; o; o >>= 1) s += __shfl_xor_sync(0xFFFFFFFFu, s, o);
        if (lane == 0) g_e2[warp] = s;

        uint2 pk;
        pk.x = pack4(q8(v0.x, SCALE_E), q8(v0.y, SCALE_E), q8(v0.z, SCALE_E), q8(v0.w, SCALE_E));
        pk.y = pack4(q8(v1.x, SCALE_E), q8(v1.y, SCALE_E), q8(v1.z, SCALE_E), q8(v1.w, SCALE_E));
        ((uint2*)(g_cq + (size_t)warp * DHEAD))[lane] = pk;
    } else {
        int i = (blockIdx.x - E2_BLOCKS) * blockDim.x + threadIdx.x;
        float4 a = ((const float4*)x)[2 * i];
        float4 b = ((const float4*)x)[2 * i + 1];
        uint2 pk;
        pk.x = pack4(q8(a.x, SCALE_X), q8(a.y, SCALE_X), q8(a.z, SCALE_X), q8(a.w, SCALE_X));
        pk.y = pack4(q8(b.x, SCALE_X), q8(b.y, SCALE_X), q8(b.z, SCALE_X), q8(b.w, SCALE_X));
        ((uint2*)g_xq)[i] = pk;
    }
}

// ---------------------------------------------------------------------------
// 1-pass INT8 GEMM (s32 acc), TILE 128x128, chunk = 128 bytes, 2 chunks.
// grid (BATCH/128, KCODES/128, H), 256 threads (8 warps: 2 M x 4 N).
// ---------------------------------------------------------------------------
__global__ __launch_bounds__(256, 2)
void dist_kernel() {
    extern __shared__ char smem[];

    const int tid = threadIdx.x;
    const int lane = tid & 31;
    const int wid = tid >> 5;
    const int warp_m = wid & 1;
    const int warp_n = wid >> 1;
    const int g  = lane >> 2;
    const int t4 = lane & 3;

    const int h  = blockIdx.z;
    const int bi = blockIdx.x * TILE_M;
    const int kj = blockIdx.y * TILE_N;

    const signed char* xg = g_xq + (size_t)bi * DFULL + (size_t)h * DHEAD;
    const signed char* eg = g_cq + ((size_t)h * KCODES + kj) * DHEAD;

    const uint32_t sbase = (uint32_t)__cvta_generic_to_shared(smem);
    const uint32_t sA[2] = {sbase, sbase + ST_BYTES};
    const uint32_t sB[2] = {sbase + 2 * ST_BYTES, sbase + 3 * ST_BYTES};

    const int lr  = lane & 7;
    const int seg = lane >> 3;
    const int a_row = ((seg & 1) ? 8 : 0) + lr;
    const int a_kb  = (seg & 2) ? 16 : 0;            // byte offset within k32
    const int b_row4 = ((lane & 16) ? 8 : 0) + lr;
    const int b_col4 = (lane & 8) ? 16 : 0;          // byte offset

    int acc[4][4][4];
#pragma unroll
    for (int mt = 0; mt < 4; mt++)
#pragma unroll
        for (int nt = 0; nt < 4; nt++)
#pragma unroll
            for (int r = 0; r < 4; r++) acc[mt][nt][r] = 0;

    // per chunk: 128 rows x 128 B each tensor -> 4 x 16B per thread each
#define COPY_CHUNK(buf, ck) do { \
        _Pragma("unroll") \
        for (int i = 0; i < 4; i++) { \
            int idx = tid + 256 * i; \
            int r = idx >> 3, s16 = idx & 7; \
            uint32_t off = (uint32_t)(r * LDB + s16 * 16); \
            CP_ASYNC16(sA[buf] + off, xg + (size_t)r * DFULL + (ck) * KCB + s16 * 16); \
            CP_ASYNC16(sB[buf] + off, eg + (size_t)r * DHEAD + (ck) * KCB + s16 * 16); \
        } \
    } while (0)

    COPY_CHUNK(0, 0);
    CP_COMMIT();

#pragma unroll 1
    for (int ck = 0; ck < NCHUNK; ck++) {
        CP_WAIT(0);
        __syncthreads();

        if (ck + 1 < NCHUNK) {
            COPY_CHUNK((ck + 1) & 1, ck + 1);
            CP_COMMIT();
        }

        const uint32_t sAc = sA[ck & 1];
        const uint32_t sBc = sB[ck & 1];

#pragma unroll
        for (int ks = 0; ks < 4; ks++) {
            const int k0 = ks * 32;                  // bytes
            uint32_t a[4][4], b[4][2];
#pragma unroll
            for (int mt = 0; mt < 4; mt++) {
                uint32_t addr = sAc +
                    (uint32_t)((warp_m * 64 + mt * 16 + a_row) * LDB + k0 + a_kb);
                LDSM_X4(a[mt][0], a[mt][1], a[mt][2], a[mt][3], addr);
            }
#pragma unroll
            for (int np = 0; np < 2; np++) {
                uint32_t addr = sBc +
                    (uint32_t)((warp_n * 32 + np * 16 + b_row4) * LDB + k0 + b_col4);
                LDSM_X4(b[2 * np][0], b[2 * np][1], b[2 * np + 1][0], b[2 * np + 1][1], addr);
            }
#pragma unroll
            for (int nt = 0; nt < 4; nt++)
#pragma unroll
                for (int mt = 0; mt < 4; mt++)
                    MMA_S8(acc[mt][nt], a[mt], b[nt][0], b[nt][1]);
        }
    }

    // ---- epilogue: dist = e2 - 2*SC*acc; fp16 store + float row/block min ----
    float e2v[4][2];
#pragma unroll
    for (int nt = 0; nt < 4; nt++) {
        int c0 = kj + warp_n * 32 + nt * 8 + 2 * t4;
        e2v[nt][0] = __ldg(&g_e2[h * KCODES + c0]);
        e2v[nt][1] = __ldg(&g_e2[h * KCODES + c0 + 1]);
    }

    __syncthreads();
    float (*redF)[4] = (float(*)[4])smem;

    const float n2sc = -2.0f * INV_SC;
#pragma unroll
    for (int mt = 0; mt < 4; mt++) {
        int r0 = warp_m * 64 + mt * 16 + g;
        int r1 = r0 + 8;
        size_t base0 = ((size_t)(bi + r0) * H + h) * KCODES + kj;
        size_t base1 = ((size_t)(bi + r1) * H + h) * KCODES + kj;
        float m0 = 3.4e38f, m1 = 3.4e38f;
#pragma unroll
        for (int nt = 0; nt < 4; nt++) {
            int c0 = warp_n * 32 + nt * 8 + 2 * t4;
            float d00 = fmaf(n2sc, (float)acc[mt][nt][0], e2v[nt][0]);
            float d01 = fmaf(n2sc, (float)acc[mt][nt][1], e2v[nt][1]);
            float d10 = fmaf(n2sc, (float)acc[mt][nt][2], e2v[nt][0]);
            float d11 = fmaf(n2sc, (float)acc[mt][nt][3], e2v[nt][1]);
            *(__half2*)&g_distH[base0 + c0] = __floats2half2_rn(d00, d01);
            *(__half2*)&g_distH[base1 + c0] = __floats2half2_rn(d10, d11);
            m0 = fminf(m0, fminf(d00, d01));
            m1 = fminf(m1, fminf(d10, d11));
        }
        m0 = fminf(m0, __shfl_xor_sync(0xFFFFFFFFu, m0, 1));
        m0 = fminf(m0, __shfl_xor_sync(0xFFFFFFFFu, m0, 2));
        m1 = fminf(m1, __shfl_xor_sync(0xFFFFFFFFu, m1, 1));
        m1 = fminf(m1, __shfl_xor_sync(0xFFFFFFFFu, m1, 2));
        if (t4 == 0) {
            redF[r0][warp_n] = m0;
            redF[r1][warp_n] = m1;
        }
    }
    __syncthreads();

    if (tid < TILE_M) {
        float best = fminf(fminf(redF[tid][0], redF[tid][1]),
                           fminf(redF[tid][2], redF[tid][3]));
        g_blkminF[((size_t)(bi + tid) * H + h) * NBLK + blockIdx.y] = best;
    }
}

// ---------------------------------------------------------------------------
// Fused re-rank + finalize: one block per batch row (all 4 heads).
// ---------------------------------------------------------------------------
__global__ __launch_bounds__(256)
void rerank_finalize_kernel(const float* __restrict__ x, const float* __restrict__ cb,
                            float* __restrict__ loss, float* __restrict__ quant,
                            float* __restrict__ codes_out) {
    const int b = blockIdx.x;
    const int tid = threadIdx.x;
    const int lane = tid & 31;
    const int wid = tid >> 5;

    __shared__ float xs[DFULL];
    __shared__ float sbm[H * NBLK];
    __shared__ float thrsh[H];
    __shared__ unsigned long long bestk[H];
    __shared__ short2 plist[H * NBLK];
    __shared__ int npairs;
    __shared__ int cand[MAXCAND];
    __shared__ int ncand;
    __shared__ float sred[256];

    ((float4*)xs)[tid] = ((const float4*)(x + (size_t)b * DFULL))[tid];
    sbm[tid] = g_blkminF[(size_t)b * (H * NBLK) + tid];
    if (tid < H) bestk[tid] = 0xFFFFFFFFFFFFFFFFull;
    if (tid == 0) { npairs = 0; ncand = 0; }
    __syncthreads();

    if (wid < H) {
        float m = fminf(sbm[wid * NBLK + lane], sbm[wid * NBLK + 32 + lane]);
#pragma unroll
        for (int o = 16; o; o >>= 1)
            m = fminf(m, __shfl_xor_sync(0xFFFFFFFFu, m, o));
        if (lane == 0) thrsh[wid] = m + MARGIN;
    }
    __syncthreads();

    {
        int h = tid >> 6;
        if (sbm[tid] <= thrsh[h]) {
            int s = atomicAdd(&npairs, 1);
            plist[s] = make_short2((short)h, (short)(tid & 63));
        }
    }
    __syncthreads();

    for (int p = wid; p < npairs; p += 8) {
        int h = plist[p].x, blk = plist[p].y;
        const float thr = thrsh[h];
        const __half* dp = g_distH + ((size_t)b * H + h) * KCODES + blk * TILE_N;
        uint2 rv = ((const uint2*)dp)[lane];
        __half2 q0 = *(__half2*)&rv.x;
        __half2 q1 = *(__half2*)&rv.y;
        float f[4] = {__low2float(q0), __high2float(q0), __low2float(q1), __high2float(q1)};
#pragma unroll
        for (int j = 0; j < 4; j++) {
            if (f[j] <= thr) {
                int s = atomicAdd(&ncand, 1);
                if (s < MAXCAND)
                    cand[s] = (h << 16) | (blk * TILE_N + lane * 4 + j);
            }
        }
    }
    __syncthreads();

    const int n = (ncand < MAXCAND) ? ncand : MAXCAND;
    for (int c = wid; c < n; c += 8) {
        int hc = cand[c] >> 16, code = cand[c] & 0xFFFF;
        const float4* e = (const float4*)(cb + ((size_t)hc * KCODES + code) * DHEAD);
        float4 e0 = e[lane * 2];
        float4 e1 = e[lane * 2 + 1];
        const float* xh = xs + hc * DHEAD + lane * 8;
        float s = 0.f;
        s = fmaf(e0.x, xh[0], s); s = fmaf(e0.y, xh[1], s);
        s = fmaf(e0.z, xh[2], s); s = fmaf(e0.w, xh[3], s);
        s = fmaf(e1.x, xh[4], s); s = fmaf(e1.y, xh[5], s);
        s = fmaf(e1.z, xh[6], s); s = fmaf(e1.w, xh[7], s);
#pragma unroll
        for (int o = 16; o; o >>= 1) s += __shfl_xor_sync(0xFFFFFFFFu, s, o);
        if (lane == 0) {
            float de = fmaf(-2.f, s, g_e2[hc * KCODES + code]);
            unsigned long long key =
                ((unsigned long long)float_key(de) << 32) | (unsigned)code;
            atomicMin(&bestk[hc], key);
        }
    }
    __syncthreads();

    float partial = 0.f;
#pragma unroll
    for (int h = 0; h < H; h++) {
        unsigned code = (unsigned)(bestk[h] & 0xFFFFFFFFu);
        if (tid == 0) codes_out[(size_t)b * H + h] = (float)code;
        float qv = cb[((size_t)h * KCODES + code) * DHEAD + tid];
        float xv = xs[h * DHEAD + tid];
        quant[(size_t)b * DFULL + (size_t)h * DHEAD + tid] = qv;
        float d = qv - xv;
        partial = fmaf(d, d, partial);
    }
    sred[tid] = partial;
    __syncthreads();
#pragma unroll
    for (int s = 128; s > 0; s >>= 1) {
        if (tid < s) sred[tid] += sred[tid + s];
        __syncthreads();
    }
    if (tid == 0) loss[b] = 0.25f * sred[0] * (1.0f / (float)DHEAD);
}

// ---------------------------------------------------------------------------
extern "C" void kernel_launch(void* const* d_in, const int* in_sizes, int n_in,
                              void* d_out, int out_size) {
    const float* x  = (const float*)d_in[0];
    const float* cb = (const float*)d_in[1];
    float* out = (float*)d_out;

    float* loss  = out;
    float* quant = out + BATCH;
    float* codes = out + BATCH + (size_t)BATCH * DFULL;

    cudaFuncSetAttribute(dist_kernel,
                         cudaFuncAttributeMaxDynamicSharedMemorySize, SMEM_DYN);

    prep_kernel<<<2 * E2_BLOCKS, 256>>>(x, cb);

    dim3 grid(BATCH / TILE_M, KCODES / TILE_N, H);
    dist_kernel<<<grid, 256, SMEM_DYN>>>();

    rerank_finalize_kernel<<<BATCH, 256>>>(x, cb, loss, quant, codes);
}

// round 16
// speedup vs baseline: 1.7844x; 1.7844x over previous
#include <cuda_runtime.h>
#include <cuda_fp16.h>
#include <cstdint>

#define H 4
#define KCODES 8192
#define DFULL 1024
#define DHEAD 256
#define BATCH 8192

#define TILE_M 128
#define TILE_N 128
#define NBLK (KCODES / TILE_N)   // 64
#define KC 64
#define NCHUNK (DHEAD / KC)      // 4
#define LD2 72                   // smem row stride in halves (64 + 8 pad)
#define MARGIN 6.0f
#define MAXCAND 256

#define ST_BYTES (TILE_M * LD2 * 2)          // 18432 B per stage per tensor
#define SMEM_DYN (4 * ST_BYTES)              // 73728 B: A0,A1,B0,B1

// Scratch
__device__ float g_e2[H * KCODES];
__device__ __half g_xh[(size_t)BATCH * DFULL];
__device__ __half g_cbh[(size_t)H * KCODES * DHEAD];
__device__ __half g_distH[(size_t)BATCH * H * KCODES];
__device__ float g_blkminF[(size_t)BATCH * H * NBLK];

__device__ __forceinline__ uint32_t float_key(float f) {
    unsigned ub = __float_as_uint(f);
    return (ub & 0x80000000u) ? ~ub : (ub | 0x80000000u);
}

#define MMA_F16(c, a, b0, b1) \
    asm volatile("mma.sync.aligned.m16n8k16.row.col.f16.f16.f16.f16 " \
        "{%0,%1}, {%2,%3,%4,%5}, {%6,%7}, {%0,%1};" \
        : "+r"((c)[0]), "+r"((c)[1]) \
        : "r"((a)[0]), "r"((a)[1]), "r"((a)[2]), "r"((a)[3]), \
          "r"(b0), "r"(b1))

#define LDSM_X4(r0, r1, r2, r3, addr) \
    asm volatile("ldmatrix.sync.aligned.m8n8.x4.shared.b16 {%0,%1,%2,%3}, [%4];" \
        : "=r"(r0), "=r"(r1), "=r"(r2), "=r"(r3) : "r"(addr))

#define CP_ASYNC16(dst, src) \
    asm volatile("cp.async.cg.shared.global [%0], [%1], 16;" :: "r"(dst), "l"(src))
#define CP_COMMIT() asm volatile("cp.async.commit_group;" ::: "memory")
#define CP_WAIT(n)  asm volatile("cp.async.wait_group %0;" :: "n"(n) : "memory")

// ---------------------------------------------------------------------------
// Merged prep: blocks [0,4096) do e2 + codebook fp16 cvt (warp per code row);
// blocks [4096,8192) do x fp16 cvt (8 floats per thread).
// ---------------------------------------------------------------------------
#define E2_BLOCKS 4096
__global__ void prep_kernel(const float* __restrict__ x, const float* __restrict__ cb) {
    if (blockIdx.x < E2_BLOCKS) {
        int warp = (blockIdx.x * blockDim.x + threadIdx.x) >> 5;
        int lane = threadIdx.x & 31;
        const float4* p = (const float4*)(cb + (size_t)warp * DHEAD);
        float4 v0 = p[lane * 2];
        float4 v1 = p[lane * 2 + 1];
        float s = v0.x * v0.x + v0.y * v0.y + v0.z * v0.z + v0.w * v0.w
                + v1.x * v1.x + v1.y * v1.y + v1.z * v1.z + v1.w * v1.w;
#pragma unroll
        for (int o = 16; o; o >>= 1) s += __shfl_xor_sync(0xFFFFFFFFu, s, o);
        if (lane == 0) g_e2[warp] = s;

        __half2 ob[4];
        ob[0] = __floats2half2_rn(v0.x, v0.y);
        ob[1] = __floats2half2_rn(v0.z, v0.w);
        ob[2] = __floats2half2_rn(v1.x, v1.y);
        ob[3] = __floats2half2_rn(v1.z, v1.w);
        ((uint4*)(g_cbh + (size_t)warp * DHEAD))[lane] = *(uint4*)ob;
    } else {
        int i = (blockIdx.x - E2_BLOCKS) * blockDim.x + threadIdx.x;
        float4 a = ((const float4*)x)[2 * i];
        float4 b = ((const float4*)x)[2 * i + 1];
        __half2 o[4];
        o[0] = __floats2half2_rn(a.x, a.y);
        o[1] = __floats2half2_rn(a.z, a.w);
        o[2] = __floats2half2_rn(b.x, b.y);
        o[3] = __floats2half2_rn(b.z, b.w);
        ((uint4*)g_xh)[i] = *(uint4*)o;
    }
}

// ---------------------------------------------------------------------------
// 1-pass FP16 GEMM (f16 acc), TILE 128x128, KC=64, one barrier per chunk.
// grid (BATCH/128, KCODES/128, H), 256 threads (8 warps: 2 M x 4 N).
// ---------------------------------------------------------------------------
__global__ __launch_bounds__(256, 3)
void dist_kernel() {
    extern __shared__ char smem[];

    const int tid = threadIdx.x;
    const int lane = tid & 31;
    const int wid = tid >> 5;
    const int warp_m = wid & 1;
    const int warp_n = wid >> 1;
    const int g  = lane >> 2;
    const int t4 = lane & 3;

    const int h  = blockIdx.z;
    const int bi = blockIdx.x * TILE_M;
    const int kj = blockIdx.y * TILE_N;

    const __half* xg = g_xh  + (size_t)bi * DFULL + (size_t)h * DHEAD;
    const __half* eg = g_cbh + ((size_t)h * KCODES + kj) * DHEAD;

    const uint32_t sbase = (uint32_t)__cvta_generic_to_shared(smem);
    const uint32_t sA[2] = {sbase, sbase + ST_BYTES};
    const uint32_t sB[2] = {sbase + 2 * ST_BYTES, sbase + 3 * ST_BYTES};

    const int lr  = lane & 7;
    const int seg = lane >> 3;
    const int a_row = ((seg & 1) ? 8 : 0) + lr;
    const int a_k   = (seg & 2) ? 8 : 0;
    const int b_row4 = ((lane & 16) ? 8 : 0) + lr;   // within np*16 pair
    const int b_col4 = (lane & 8) ? 8 : 0;

    uint32_t acc[4][4][2];
#pragma unroll
    for (int mt = 0; mt < 4; mt++)
#pragma unroll
        for (int nt = 0; nt < 4; nt++) {
            acc[mt][nt][0] = 0u;
            acc[mt][nt][1] = 0u;
        }

#define COPY_CHUNK(buf, ck) do { \
        _Pragma("unroll") \
        for (int i = 0; i < 4; i++) { \
            int idx = tid + 256 * i; \
            int r = idx >> 3, s8 = idx & 7; \
            uint32_t off = (uint32_t)(r * LD2 + s8 * 8) * 2u; \
            CP_ASYNC16(sA[buf] + off, xg + (size_t)r * DFULL + (ck) * KC + s8 * 8); \
            CP_ASYNC16(sB[buf] + off, eg + (size_t)r * DHEAD + (ck) * KC + s8 * 8); \
        } \
    } while (0)

    float e2v[4][2];

    COPY_CHUNK(0, 0);
    CP_COMMIT();

#pragma unroll 1
    for (int ck = 0; ck < NCHUNK; ck++) {
        CP_WAIT(0);          // chunk ck copy complete
        __syncthreads();     // + all warps done computing chunk ck-1 (buffer free)

        if (ck + 1 < NCHUNK) {
            COPY_CHUNK((ck + 1) & 1, ck + 1);
            CP_COMMIT();
        } else {
            // hoist epilogue e2 loads: overlap L2 latency with last chunk's MMAs
#pragma unroll
            for (int nt = 0; nt < 4; nt++) {
                int c0 = kj + warp_n * 32 + nt * 8 + 2 * t4;
                e2v[nt][0] = __ldg(&g_e2[h * KCODES + c0]);
                e2v[nt][1] = __ldg(&g_e2[h * KCODES + c0 + 1]);
            }
        }

        const uint32_t sAc = sA[ck & 1];
        const uint32_t sBc = sB[ck & 1];

#pragma unroll
        for (int ks = 0; ks < 4; ks++) {
            const int k0 = ks * 16;
            uint32_t a[4][4], b[4][2];
#pragma unroll
            for (int mt = 0; mt < 4; mt++) {
                uint32_t addr = sAc +
                    (uint32_t)(((warp_m * 64 + mt * 16 + a_row) * LD2 + k0 + a_k) * 2);
                LDSM_X4(a[mt][0], a[mt][1], a[mt][2], a[mt][3], addr);
            }
#pragma unroll
            for (int np = 0; np < 2; np++) {
                uint32_t addr = sBc +
                    (uint32_t)(((warp_n * 32 + np * 16 + b_row4) * LD2 + k0 + b_col4) * 2);
                LDSM_X4(b[2 * np][0], b[2 * np][1], b[2 * np + 1][0], b[2 * np + 1][1], addr);
            }
#pragma unroll
            for (int nt = 0; nt < 4; nt++)
#pragma unroll
                for (int mt = 0; mt < 4; mt++)
                    MMA_F16(acc[mt][nt], a[mt], b[nt][0], b[nt][1]);
        }
    }

    // ---- epilogue: dist = e2 - 2*acc; fp16 store + float row/block min ----
    __syncthreads();    // all compute done before overlaying redF on A buffer
    float (*redF)[4] = (float(*)[4])smem;

#pragma unroll
    for (int mt = 0; mt < 4; mt++) {
        int r0 = warp_m * 64 + mt * 16 + g;
        int r1 = r0 + 8;
        size_t base0 = ((size_t)(bi + r0) * H + h) * KCODES + kj;
        size_t base1 = ((size_t)(bi + r1) * H + h) * KCODES + kj;
        float m0 = 3.4e38f, m1 = 3.4e38f;
#pragma unroll
        for (int nt = 0; nt < 4; nt++) {
            int c0 = warp_n * 32 + nt * 8 + 2 * t4;
            float2 lo = __half22float2(*(__half2*)&acc[mt][nt][0]);
            float2 hi = __half22float2(*(__half2*)&acc[mt][nt][1]);
            float d00 = fmaf(-2.f, lo.x, e2v[nt][0]);
            float d01 = fmaf(-2.f, lo.y, e2v[nt][1]);
            float d10 = fmaf(-2.f, hi.x, e2v[nt][0]);
            float d11 = fmaf(-2.f, hi.y, e2v[nt][1]);
            *(__half2*)&g_distH[base0 + c0] = __floats2half2_rn(d00, d01);
            *(__half2*)&g_distH[base1 + c0] = __floats2half2_rn(d10, d11);
            m0 = fminf(m0, fminf(d00, d01));
            m1 = fminf(m1, fminf(d10, d11));
        }
        m0 = fminf(m0, __shfl_xor_sync(0xFFFFFFFFu, m0, 1));
        m0 = fminf(m0, __shfl_xor_sync(0xFFFFFFFFu, m0, 2));
        m1 = fminf(m1, __shfl_xor_sync(0xFFFFFFFFu, m1, 1));
        m1 = fminf(m1, __shfl_xor_sync(0xFFFFFFFFu, m1, 2));
        if (t4 == 0) {
            redF[r0][warp_n] = m0;
            redF[r1][warp_n] = m1;
        }
    }
    __syncthreads();

    if (tid < TILE_M) {
        float best = fminf(fminf(redF[tid][0], redF[tid][1]),
                           fminf(redF[tid][2], redF[tid][3]));
        g_blkminF[((size_t)(bi + tid) * H + h) * NBLK + blockIdx.y] = best;
    }
}

// ---------------------------------------------------------------------------
// Fused re-rank + finalize: one block per batch row (all 4 heads).
// ---------------------------------------------------------------------------
__global__ __launch_bounds__(256)
void rerank_finalize_kernel(const float* __restrict__ x, const float* __restrict__ cb,
                            float* __restrict__ loss, float* __restrict__ quant,
                            float* __restrict__ codes_out) {
    const int b = blockIdx.x;
    const int tid = threadIdx.x;
    const int lane = tid & 31;
    const int wid = tid >> 5;

    __shared__ float xs[DFULL];
    __shared__ float sbm[H * NBLK];
    __shared__ float thrsh[H];
    __shared__ unsigned long long bestk[H];
    __shared__ short2 plist[H * NBLK];
    __shared__ int npairs;
    __shared__ int cand[MAXCAND];
    __shared__ int ncand;
    __shared__ float sred[256];

    ((float4*)xs)[tid] = ((const float4*)(x + (size_t)b * DFULL))[tid];
    sbm[tid] = g_blkminF[(size_t)b * (H * NBLK) + tid];
    if (tid < H) bestk[tid] = 0xFFFFFFFFFFFFFFFFull;
    if (tid == 0) { npairs = 0; ncand = 0; }
    __syncthreads();

    if (wid < H) {
        float m = fminf(sbm[wid * NBLK + lane], sbm[wid * NBLK + 32 + lane]);
#pragma unroll
        for (int o = 16; o; o >>= 1)
            m = fminf(m, __shfl_xor_sync(0xFFFFFFFFu, m, o));
        if (lane == 0) thrsh[wid] = m + MARGIN;
    }
    __syncthreads();

    {
        int h = tid >> 6;
        if (sbm[tid] <= thrsh[h]) {
            int s = atomicAdd(&npairs, 1);
            plist[s] = make_short2((short)h, (short)(tid & 63));
        }
    }
    __syncthreads();

    for (int p = wid; p < npairs; p += 8) {
        int h = plist[p].x, blk = plist[p].y;
        const float thr = thrsh[h];
        const __half* dp = g_distH + ((size_t)b * H + h) * KCODES + blk * TILE_N;
        uint2 rv = ((const uint2*)dp)[lane];
        __half2 q0 = *(__half2*)&rv.x;
        __half2 q1 = *(__half2*)&rv.y;
        float f[4] = {__low2float(q0), __high2float(q0), __low2float(q1), __high2float(q1)};
#pragma unroll
        for (int j = 0; j < 4; j++) {
            if (f[j] <= thr) {
                int s = atomicAdd(&ncand, 1);
                if (s < MAXCAND)
                    cand[s] = (h << 16) | (blk * TILE_N + lane * 4 + j);
            }
        }
    }
    __syncthreads();

    const int n = (ncand < MAXCAND) ? ncand : MAXCAND;
    for (int c = wid; c < n; c += 8) {
        int hc = cand[c] >> 16, code = cand[c] & 0xFFFF;
        const float4* e = (const float4*)(cb + ((size_t)hc * KCODES + code) * DHEAD);
        float4 e0 = e[lane * 2];
        float4 e1 = e[lane * 2 + 1];
        const float* xh = xs + hc * DHEAD + lane * 8;
        float s = 0.f;
        s = fmaf(e0.x, xh[0], s); s = fmaf(e0.y, xh[1], s);
        s = fmaf(e0.z, xh[2], s); s = fmaf(e0.w, xh[3], s);
        s = fmaf(e1.x, xh[4], s); s = fmaf(e1.y, xh[5], s);
        s = fmaf(e1.z, xh[6], s); s = fmaf(e1.w, xh[7], s);
#pragma unroll
        for (int o = 16; o; o >>= 1) s += __shfl_xor_sync(0xFFFFFFFFu, s, o);
        if (lane == 0) {
            float de = fmaf(-2.f, s, g_e2[hc * KCODES + code]);
            unsigned long long key =
                ((unsigned long long)float_key(de) << 32) | (unsigned)code;
            atomicMin(&bestk[hc], key);
        }
    }
    __syncthreads();

    float partial = 0.f;
#pragma unroll
    for (int h = 0; h < H; h++) {
        unsigned code = (unsigned)(bestk[h] & 0xFFFFFFFFu);
        if (tid == 0) codes_out[(size_t)b * H + h] = (float)code;
        float qv = cb[((size_t)h * KCODES + code) * DHEAD + tid];
        float xv = xs[h * DHEAD + tid];
        quant[(size_t)b * DFULL + (size_t)h * DHEAD + tid] = qv;
        float d = qv - xv;
        partial = fmaf(d, d, partial);
    }
    sred[tid] = partial;
    __syncthreads();
#pragma unroll
    for (int s = 128; s > 0; s >>= 1) {
        if (tid < s) sred[tid] += sred[tid + s];
        __syncthreads();
    }
    if (tid == 0) loss[b] = 0.25f * sred[0] * (1.0f / (float)DHEAD);
}

// ---------------------------------------------------------------------------
extern "C" void kernel_launch(void* const* d_in, const int* in_sizes, int n_in,
                              void* d_out, int out_size) {
    const float* x  = (const float*)d_in[0];
    const float* cb = (const float*)d_in[1];
    float* out = (float*)d_out;

    float* loss  = out;
    float* quant = out + BATCH;
    float* codes = out + BATCH + (size_t)BATCH * DFULL;

    cudaFuncSetAttribute(dist_kernel,
                         cudaFuncAttributeMaxDynamicSharedMemorySize, SMEM_DYN);

    prep_kernel<<<2 * E2_BLOCKS, 256>>>(x, cb);

    dim3 grid(BATCH / TILE_M, KCODES / TILE_N, H);
    dist_kernel<<<grid, 256, SMEM_DYN>>>();

    rerank_finalize_kernel<<<BATCH, 256>>>(x, cb, loss, quant, codes);
}

// round 17
// speedup vs baseline: 1.9008x; 1.0652x over previous
#include <cuda_runtime.h>
#include <cuda_fp16.h>
#include <cstdint>

#define H 4
#define KCODES 8192
#define DFULL 1024
#define DHEAD 256
#define BATCH 8192

#define TILE_M 128
#define TILE_N 128
#define NBLK (KCODES / TILE_N)   // 64
#define KC 64
#define NCHUNK (DHEAD / KC)      // 4
#define LD2 72                   // smem row stride in halves (64 + 8 pad)
#define MARGIN 6.0f
#define MAXCAND 256

#define ST_BYTES (TILE_M * LD2 * 2)          // 18432 B per stage per tensor
#define SMEM_DYN (4 * ST_BYTES + 512)        // 74240 B: A0,A1,B0,B1 + e2s (3 CTAs/SM fits 228KB)

// Scratch
__device__ float g_e2[H * KCODES];
__device__ __half g_xh[(size_t)BATCH * DFULL];
__device__ __half g_cbh[(size_t)H * KCODES * DHEAD];
__device__ __half g_distH[(size_t)BATCH * H * KCODES];
__device__ float g_blkminF[(size_t)BATCH * H * NBLK];

__device__ __forceinline__ uint32_t float_key(float f) {
    unsigned ub = __float_as_uint(f);
    return (ub & 0x80000000u) ? ~ub : (ub | 0x80000000u);
}

#define MMA_F16(c, a, b0, b1) \
    asm volatile("mma.sync.aligned.m16n8k16.row.col.f16.f16.f16.f16 " \
        "{%0,%1}, {%2,%3,%4,%5}, {%6,%7}, {%0,%1};" \
        : "+r"((c)[0]), "+r"((c)[1]) \
        : "r"((a)[0]), "r"((a)[1]), "r"((a)[2]), "r"((a)[3]), \
          "r"(b0), "r"(b1))

#define LDSM_X4(r0, r1, r2, r3, addr) \
    asm volatile("ldmatrix.sync.aligned.m8n8.x4.shared.b16 {%0,%1,%2,%3}, [%4];" \
        : "=r"(r0), "=r"(r1), "=r"(r2), "=r"(r3) : "r"(addr))

#define CP_ASYNC16(dst, src) \
    asm volatile("cp.async.cg.shared.global [%0], [%1], 16;" :: "r"(dst), "l"(src))
#define CP_COMMIT() asm volatile("cp.async.commit_group;" ::: "memory")
#define CP_WAIT(n)  asm volatile("cp.async.wait_group %0;" :: "n"(n) : "memory")

// ---------------------------------------------------------------------------
// Merged prep: blocks [0,4096) do e2 + codebook fp16 cvt (warp per code row);
// blocks [4096,8192) do x fp16 cvt (8 floats per thread).
// ---------------------------------------------------------------------------
#define E2_BLOCKS 4096
__global__ void prep_kernel(const float* __restrict__ x, const float* __restrict__ cb) {
    if (blockIdx.x < E2_BLOCKS) {
        int warp = (blockIdx.x * blockDim.x + threadIdx.x) >> 5;
        int lane = threadIdx.x & 31;
        const float4* p = (const float4*)(cb + (size_t)warp * DHEAD);
        float4 v0 = p[lane * 2];
        float4 v1 = p[lane * 2 + 1];
        float s = v0.x * v0.x + v0.y * v0.y + v0.z * v0.z + v0.w * v0.w
                + v1.x * v1.x + v1.y * v1.y + v1.z * v1.z + v1.w * v1.w;
#pragma unroll
        for (int o = 16; o; o >>= 1) s += __shfl_xor_sync(0xFFFFFFFFu, s, o);
        if (lane == 0) g_e2[warp] = s;

        __half2 ob[4];
        ob[0] = __floats2half2_rn(v0.x, v0.y);
        ob[1] = __floats2half2_rn(v0.z, v0.w);
        ob[2] = __floats2half2_rn(v1.x, v1.y);
        ob[3] = __floats2half2_rn(v1.z, v1.w);
        ((uint4*)(g_cbh + (size_t)warp * DHEAD))[lane] = *(uint4*)ob;
    } else {
        int i = (blockIdx.x - E2_BLOCKS) * blockDim.x + threadIdx.x;
        float4 a = ((const float4*)x)[2 * i];
        float4 b = ((const float4*)x)[2 * i + 1];
        __half2 o[4];
        o[0] = __floats2half2_rn(a.x, a.y);
        o[1] = __floats2half2_rn(a.z, a.w);
        o[2] = __floats2half2_rn(b.x, b.y);
        o[3] = __floats2half2_rn(b.z, b.w);
        ((uint4*)g_xh)[i] = *(uint4*)o;
    }
}

// ---------------------------------------------------------------------------
// 1-pass FP16 GEMM (f16 acc), TILE 128x128, KC=64, one barrier per chunk.
// e2 cached in dynamic smem at kernel start (latency hidden in prologue).
// grid (BATCH/128, KCODES/128, H), 256 threads (8 warps: 2 M x 4 N).
// ---------------------------------------------------------------------------
__global__ __launch_bounds__(256, 3)
void dist_kernel() {
    extern __shared__ char smem[];
    float* e2s = (float*)(smem + 4 * ST_BYTES);

    const int tid = threadIdx.x;
    const int lane = tid & 31;
    const int wid = tid >> 5;
    const int warp_m = wid & 1;
    const int warp_n = wid >> 1;
    const int g  = lane >> 2;
    const int t4 = lane & 3;

    const int h  = blockIdx.z;
    const int bi = blockIdx.x * TILE_M;
    const int kj = blockIdx.y * TILE_N;

    if (tid < TILE_N) e2s[tid] = g_e2[h * KCODES + kj + tid];

    const __half* xg = g_xh  + (size_t)bi * DFULL + (size_t)h * DHEAD;
    const __half* eg = g_cbh + ((size_t)h * KCODES + kj) * DHEAD;

    const uint32_t sbase = (uint32_t)__cvta_generic_to_shared(smem);
    const uint32_t sA[2] = {sbase, sbase + ST_BYTES};
    const uint32_t sB[2] = {sbase + 2 * ST_BYTES, sbase + 3 * ST_BYTES};

    const int lr  = lane & 7;
    const int seg = lane >> 3;
    const int a_row = ((seg & 1) ? 8 : 0) + lr;
    const int a_k   = (seg & 2) ? 8 : 0;
    const int b_row4 = ((lane & 16) ? 8 : 0) + lr;   // within np*16 pair
    const int b_col4 = (lane & 8) ? 8 : 0;

    uint32_t acc[4][4][2];
#pragma unroll
    for (int mt = 0; mt < 4; mt++)
#pragma unroll
        for (int nt = 0; nt < 4; nt++) {
            acc[mt][nt][0] = 0u;
            acc[mt][nt][1] = 0u;
        }

#define COPY_CHUNK(buf, ck) do { \
        _Pragma("unroll") \
        for (int i = 0; i < 4; i++) { \
            int idx = tid + 256 * i; \
            int r = idx >> 3, s8 = idx & 7; \
            uint32_t off = (uint32_t)(r * LD2 + s8 * 8) * 2u; \
            CP_ASYNC16(sA[buf] + off, xg + (size_t)r * DFULL + (ck) * KC + s8 * 8); \
            CP_ASYNC16(sB[buf] + off, eg + (size_t)r * DHEAD + (ck) * KC + s8 * 8); \
        } \
    } while (0)

    COPY_CHUNK(0, 0);
    CP_COMMIT();

#pragma unroll 1
    for (int ck = 0; ck < NCHUNK; ck++) {
        CP_WAIT(0);          // chunk ck copy complete
        __syncthreads();     // + all warps done computing chunk ck-1 (buffer free)

        if (ck + 1 < NCHUNK) {
            COPY_CHUNK((ck + 1) & 1, ck + 1);
            CP_COMMIT();
        }

        const uint32_t sAc = sA[ck & 1];
        const uint32_t sBc = sB[ck & 1];

#pragma unroll
        for (int ks = 0; ks < 4; ks++) {
            const int k0 = ks * 16;
            uint32_t a[4][4], b[4][2];
#pragma unroll
            for (int mt = 0; mt < 4; mt++) {
                uint32_t addr = sAc +
                    (uint32_t)(((warp_m * 64 + mt * 16 + a_row) * LD2 + k0 + a_k) * 2);
                LDSM_X4(a[mt][0], a[mt][1], a[mt][2], a[mt][3], addr);
            }
#pragma unroll
            for (int np = 0; np < 2; np++) {
                uint32_t addr = sBc +
                    (uint32_t)(((warp_n * 32 + np * 16 + b_row4) * LD2 + k0 + b_col4) * 2);
                LDSM_X4(b[2 * np][0], b[2 * np][1], b[2 * np + 1][0], b[2 * np + 1][1], addr);
            }
#pragma unroll
            for (int nt = 0; nt < 4; nt++)
#pragma unroll
                for (int mt = 0; mt < 4; mt++)
                    MMA_F16(acc[mt][nt], a[mt], b[nt][0], b[nt][1]);
        }
    }

    // ---- epilogue: dist = e2 - 2*acc; fp16 store + float row/block min ----
    __syncthreads();    // all compute done before overlaying redF on A buffer
    float (*redF)[4] = (float(*)[4])smem;

#pragma unroll
    for (int mt = 0; mt < 4; mt++) {
        int r0 = warp_m * 64 + mt * 16 + g;
        int r1 = r0 + 8;
        size_t base0 = ((size_t)(bi + r0) * H + h) * KCODES + kj;
        size_t base1 = ((size_t)(bi + r1) * H + h) * KCODES + kj;
        float m0 = 3.4e38f, m1 = 3.4e38f;
#pragma unroll
        for (int nt = 0; nt < 4; nt++) {
            int c0 = warp_n * 32 + nt * 8 + 2 * t4;
            float e20 = e2s[c0];
            float e21 = e2s[c0 + 1];
            float2 lo = __half22float2(*(__half2*)&acc[mt][nt][0]);
            float2 hi = __half22float2(*(__half2*)&acc[mt][nt][1]);
            float d00 = fmaf(-2.f, lo.x, e20);
            float d01 = fmaf(-2.f, lo.y, e21);
            float d10 = fmaf(-2.f, hi.x, e20);
            float d11 = fmaf(-2.f, hi.y, e21);
            *(__half2*)&g_distH[base0 + c0] = __floats2half2_rn(d00, d01);
            *(__half2*)&g_distH[base1 + c0] = __floats2half2_rn(d10, d11);
            m0 = fminf(m0, fminf(d00, d01));
            m1 = fminf(m1, fminf(d10, d11));
        }
        m0 = fminf(m0, __shfl_xor_sync(0xFFFFFFFFu, m0, 1));
        m0 = fminf(m0, __shfl_xor_sync(0xFFFFFFFFu, m0, 2));
        m1 = fminf(m1, __shfl_xor_sync(0xFFFFFFFFu, m1, 1));
        m1 = fminf(m1, __shfl_xor_sync(0xFFFFFFFFu, m1, 2));
        if (t4 == 0) {
            redF[r0][warp_n] = m0;
            redF[r1][warp_n] = m1;
        }
    }
    __syncthreads();

    if (tid < TILE_M) {
        float best = fminf(fminf(redF[tid][0], redF[tid][1]),
                           fminf(redF[tid][2], redF[tid][3]));
        g_blkminF[((size_t)(bi + tid) * H + h) * NBLK + blockIdx.y] = best;
    }
}

// ---------------------------------------------------------------------------
// Fused re-rank + finalize: one block per batch row (all 4 heads).
// ---------------------------------------------------------------------------
__global__ __launch_bounds__(256)
void rerank_finalize_kernel(const float* __restrict__ x, const float* __restrict__ cb,
                            float* __restrict__ loss, float* __restrict__ quant,
                            float* __restrict__ codes_out) {
    const int b = blockIdx.x;
    const int tid = threadIdx.x;
    const int lane = tid & 31;
    const int wid = tid >> 5;

    __shared__ float xs[DFULL];
    __shared__ float sbm[H * NBLK];
    __shared__ float thrsh[H];
    __shared__ unsigned long long bestk[H];
    __shared__ short2 plist[H * NBLK];
    __shared__ int npairs;
    __shared__ int cand[MAXCAND];
    __shared__ int ncand;
    __shared__ float sred[256];

    ((float4*)xs)[tid] = ((const float4*)(x + (size_t)b * DFULL))[tid];
    sbm[tid] = g_blkminF[(size_t)b * (H * NBLK) + tid];
    if (tid < H) bestk[tid] = 0xFFFFFFFFFFFFFFFFull;
    if (tid == 0) { npairs = 0; ncand = 0; }
    __syncthreads();

    if (wid < H) {
        float m = fminf(sbm[wid * NBLK + lane], sbm[wid * NBLK + 32 + lane]);
#pragma unroll
        for (int o = 16; o; o >>= 1)
            m = fminf(m, __shfl_xor_sync(0xFFFFFFFFu, m, o));
        if (lane == 0) thrsh[wid] = m + MARGIN;
    }
    __syncthreads();

    {
        int h = tid >> 6;
        if (sbm[tid] <= thrsh[h]) {
            int s = atomicAdd(&npairs, 1);
            plist[s] = make_short2((short)h, (short)(tid & 63));
        }
    }
    __syncthreads();

    for (int p = wid; p < npairs; p += 8) {
        int h = plist[p].x, blk = plist[p].y;
        const float thr = thrsh[h];
        const __half* dp = g_distH + ((size_t)b * H + h) * KCODES + blk * TILE_N;
        uint2 rv = ((const uint2*)dp)[lane];
        __half2 q0 = *(__half2*)&rv.x;
        __half2 q1 = *(__half2*)&rv.y;
        float f[4] = {__low2float(q0), __high2float(q0), __low2float(q1), __high2float(q1)};
#pragma unroll
        for (int j = 0; j < 4; j++) {
            if (f[j] <= thr) {
                int s = atomicAdd(&ncand, 1);
                if (s < MAXCAND)
                    cand[s] = (h << 16) | (blk * TILE_N + lane * 4 + j);
            }
        }
    }
    __syncthreads();

    const int n = (ncand < MAXCAND) ? ncand : MAXCAND;
    for (int c = wid; c < n; c += 8) {
        int hc = cand[c] >> 16, code = cand[c] & 0xFFFF;
        const float4* e = (const float4*)(cb + ((size_t)hc * KCODES + code) * DHEAD);
        float4 e0 = e[lane * 2];
        float4 e1 = e[lane * 2 + 1];
        const float* xh = xs + hc * DHEAD + lane * 8;
        float s = 0.f;
        s = fmaf(e0.x, xh[0], s); s = fmaf(e0.y, xh[1], s);
        s = fmaf(e0.z, xh[2], s); s = fmaf(e0.w, xh[3], s);
        s = fmaf(e1.x, xh[4], s); s = fmaf(e1.y, xh[5], s);
        s = fmaf(e1.z, xh[6], s); s = fmaf(e1.w, xh[7], s);
#pragma unroll
        for (int o = 16; o; o >>= 1) s += __shfl_xor_sync(0xFFFFFFFFu, s, o);
        if (lane == 0) {
            float de = fmaf(-2.f, s, g_e2[hc * KCODES + code]);
            unsigned long long key =
                ((unsigned long long)float_key(de) << 32) | (unsigned)code;
            atomicMin(&bestk[hc], key);
        }
    }
    __syncthreads();

    float partial = 0.f;
#pragma unroll
    for (int h = 0; h < H; h++) {
        unsigned code = (unsigned)(bestk[h] & 0xFFFFFFFFu);
        if (tid == 0) codes_out[(size_t)b * H + h] = (float)code;
        float qv = cb[((size_t)h * KCODES + code) * DHEAD + tid];
        float xv = xs[h * DHEAD + tid];
        quant[(size_t)b * DFULL + (size_t)h * DHEAD + tid] = qv;
        float d = qv - xv;
        partial = fmaf(d, d, partial);
    }
    sred[tid] = partial;
    __syncthreads();
#pragma unroll
    for (int s = 128; s > 0; s >>= 1) {
        if (tid < s) sred[tid] += sred[tid + s];
        __syncthreads();
    }
    if (tid == 0) loss[b] = 0.25f * sred[0] * (1.0f / (float)DHEAD);
}

// ---------------------------------------------------------------------------
extern "C" void kernel_launch(void* const* d_in, const int* in_sizes, int n_in,
                              void* d_out, int out_size) {
    const float* x  = (const float*)d_in[0];
    const float* cb = (const float*)d_in[1];
    float* out = (float*)d_out;

    float* loss  = out;
    float* quant = out + BATCH;
    float* codes = out + BATCH + (size_t)BATCH * DFULL;

    cudaFuncSetAttribute(dist_kernel,
                         cudaFuncAttributeMaxDynamicSharedMemorySize, SMEM_DYN);

    prep_kernel<<<2 * E2_BLOCKS, 256>>>(x, cb);

    dim3 grid(BATCH / TILE_M, KCODES / TILE_N, H);
    dist_kernel<<<grid, 256, SMEM_DYN>>>();

    rerank_finalize_kernel<<<BATCH, 256>>>(x, cb, loss, quant, codes);
}